// round 17
// baseline (speedup 1.0000x reference)
#include <cuda_runtime.h>

#define B_ 256
#define S_ 196
#define R_ 1024
#define H_ 512

#define KSPLIT 8
#define KCHUNK (R_ / KSPLIT)     // 128

// GEMM tiling for k_h2att (R13 best-measured config)
#define BM 64
#define BN 64
#define BK 16
#define NTILES (KCHUNK / BK)     // 8

#define SQ (S_ / 4)              // 49 scores per fused block

// Scratch (no allocations allowed anywhere)
__device__ float g_att_h_part[KSPLIT * B_ * H_];
__device__ float g_scores[B_ * S_];
__device__ unsigned g_cnt[B_];   // per-b arrival counter (generation-robust)

__device__ __forceinline__ float tanh_fast(float x) {
    float y;
    asm("tanh.approx.f32 %0, %1;" : "=f"(y) : "f"(x));
    return y;
}

// ---------------------------------------------------------------------------
// Kernel A: partial att_h = hidden @ W^T (+bias on z==0 split).
// grid (8, 4, KSPLIT=8) = 256 blocks, 256 threads, 4x4 micro-tile,
// ping-pong smem + register staging (R13 config, measured 13.0us).
// ---------------------------------------------------------------------------
__global__ void __launch_bounds__(256)
k_h2att(const float* __restrict__ hidden,
        const float* __restrict__ W,
        const float* __restrict__ bias) {
    __shared__ __align__(16) float As[2][BK][BM + 4];   // [buf][kk][b-row]
    __shared__ __align__(16) float Bs[2][BK][BN + 4];   // [buf][kk][h-col]
    const int h0 = blockIdx.x * BN;
    const int b0 = blockIdx.y * BM;
    const int z  = blockIdx.z;
    const int tid = threadIdx.x;

    const int lrow = tid >> 2;            // 0..63 (row to stage)
    const int lk   = (tid & 3) * 4;       // 0,4,8,12 (k quad)

    const int tx4 = (tid & 15) * 4;       // h micro col
    const int ty4 = (tid >> 4) * 4;       // b micro row

    float acc[4][4] = {};

    const int kbeg = z * KCHUNK;
    const float* ha = &hidden[(size_t)(b0 + lrow) * R_ + kbeg + lk];
    const float* wa = &W[(size_t)(h0 + lrow) * R_ + kbeg + lk];

    {
        float4 av = *(const float4*)ha;
        float4 bv = *(const float4*)wa;
        As[0][lk + 0][lrow] = av.x;
        As[0][lk + 1][lrow] = av.y;
        As[0][lk + 2][lrow] = av.z;
        As[0][lk + 3][lrow] = av.w;
        Bs[0][lk + 0][lrow] = bv.x;
        Bs[0][lk + 1][lrow] = bv.y;
        Bs[0][lk + 2][lrow] = bv.z;
        Bs[0][lk + 3][lrow] = bv.w;
    }
    __syncthreads();

    #pragma unroll
    for (int i = 0; i < NTILES; i++) {
        float4 av, bv;
        if (i + 1 < NTILES) {              // issue next tile's loads early
            av = *(const float4*)(ha + (i + 1) * BK);
            bv = *(const float4*)(wa + (i + 1) * BK);
        }

        const int p = i & 1;
        #pragma unroll
        for (int kk = 0; kk < BK; kk++) {
            float4 a = *(const float4*)&As[p][kk][ty4];
            float4 b = *(const float4*)&Bs[p][kk][tx4];
            acc[0][0] = fmaf(a.x, b.x, acc[0][0]);
            acc[0][1] = fmaf(a.x, b.y, acc[0][1]);
            acc[0][2] = fmaf(a.x, b.z, acc[0][2]);
            acc[0][3] = fmaf(a.x, b.w, acc[0][3]);
            acc[1][0] = fmaf(a.y, b.x, acc[1][0]);
            acc[1][1] = fmaf(a.y, b.y, acc[1][1]);
            acc[1][2] = fmaf(a.y, b.z, acc[1][2]);
            acc[1][3] = fmaf(a.y, b.w, acc[1][3]);
            acc[2][0] = fmaf(a.z, b.x, acc[2][0]);
            acc[2][1] = fmaf(a.z, b.y, acc[2][1]);
            acc[2][2] = fmaf(a.z, b.z, acc[2][2]);
            acc[2][3] = fmaf(a.z, b.w, acc[2][3]);
            acc[3][0] = fmaf(a.w, b.x, acc[3][0]);
            acc[3][1] = fmaf(a.w, b.y, acc[3][1]);
            acc[3][2] = fmaf(a.w, b.z, acc[3][2]);
            acc[3][3] = fmaf(a.w, b.w, acc[3][3]);
        }

        if (i + 1 < NTILES) {
            const int q = (i + 1) & 1;
            As[q][lk + 0][lrow] = av.x;
            As[q][lk + 1][lrow] = av.y;
            As[q][lk + 2][lrow] = av.z;
            As[q][lk + 3][lrow] = av.w;
            Bs[q][lk + 0][lrow] = bv.x;
            Bs[q][lk + 1][lrow] = bv.y;
            Bs[q][lk + 2][lrow] = bv.z;
            Bs[q][lk + 3][lrow] = bv.w;
            __syncthreads();
        }
    }

    float4 bias4 = make_float4(0.f, 0.f, 0.f, 0.f);
    if (z == 0) bias4 = *(const float4*)&bias[h0 + tx4];

    float* outp = g_att_h_part + (size_t)z * B_ * H_;
    #pragma unroll
    for (int i = 0; i < 4; i++) {
        float4 r = make_float4(acc[i][0] + bias4.x,
                               acc[i][1] + bias4.y,
                               acc[i][2] + bias4.z,
                               acc[i][3] + bias4.w);
        *(float4*)&outp[(size_t)(b0 + ty4 + i) * H_ + h0 + tx4] = r;
    }
}

// ---------------------------------------------------------------------------
// Kernel B: fused scores + softmax + pooling. grid (4, B), 256 threads.
// Block (b,q): computes scores for quarter q of b's S, arrives on g_cnt[b]
// (release), spins until all 4 quarters done (per-b handshake — all 1024
// blocks are co-resident so this cannot deadlock), then softmax (identical,
// deterministic in every block) + pools r-chunk q. q==0 writes weight.
// Generation-robust counter: target = r - (r & 3) + 4 — no reset needed.
// ---------------------------------------------------------------------------
__global__ void __launch_bounds__(256)
k_sp(const float* __restrict__ p_att,
     const float* __restrict__ in_w,
     const float* __restrict__ alpha_w,
     const float* __restrict__ alpha_b,
     const float* __restrict__ att_feats,
     float* __restrict__ weight_out,
     float* __restrict__ att_res) {
    __shared__ __align__(16) float sh_ah[H_];
    __shared__ __align__(16) float sh_al[H_];
    __shared__ float ws[S_];
    __shared__ float red[8];
    const int b = blockIdx.y;
    const int q = blockIdx.x;          // quarter 0..3
    const int tid = threadIdx.x;
    const int warp = tid >> 5, lane = tid & 31;

    // --- stage att_h (reduce KSPLIT partials) + alpha into smem ---
    #pragma unroll
    for (int i = tid; i < H_; i += 256) {
        size_t o = (size_t)b * H_ + i;
        float v = 0.f;
        #pragma unroll
        for (int p = 0; p < KSPLIT; p++)
            v += g_att_h_part[(size_t)p * B_ * H_ + o];
        sh_ah[i] = v;
        sh_al[i] = alpha_w[i];
    }
    __syncthreads();

    // --- scores for this block's quarter: s in [q*49, (q+1)*49) ---
    const float4* ah4 = (const float4*)sh_ah;
    const float4* al4 = (const float4*)sh_al;
    const float ab0 = alpha_b[0];

    for (int sl = warp; sl < SQ; sl += 8) {
        const int s = q * SQ + sl;
        const float iw = in_w[b * S_ + s];
        const float4* p4 = (const float4*)(p_att + ((size_t)b * S_ + s) * H_);
        float acc = 0.f;
        #pragma unroll
        for (int j = 0; j < 4; j++) {
            float4 p = p4[j * 32 + lane];
            float4 a = ah4[j * 32 + lane];
            float4 w = al4[j * 32 + lane];
            acc += tanh_fast(fmaf(iw, p.x, a.x)) * w.x;
            acc += tanh_fast(fmaf(iw, p.y, a.y)) * w.y;
            acc += tanh_fast(fmaf(iw, p.z, a.z)) * w.z;
            acc += tanh_fast(fmaf(iw, p.w, a.w)) * w.w;
        }
        #pragma unroll
        for (int o = 16; o; o >>= 1)
            acc += __shfl_xor_sync(0xffffffffu, acc, o);
        if (lane == 0)
            g_scores[b * S_ + s] = acc + ab0;
    }

    // --- per-b handshake: release our quarter, wait for all 4 ---
    __threadfence();                           // publish score writes
    __syncthreads();
    if (tid == 0) {
        unsigned r = atomicAdd(&g_cnt[b], 1u);
        unsigned target = r - (r & 3u) + 4u;   // end of this generation
        while (*(volatile unsigned*)&g_cnt[b] < target)
            __nanosleep(32);
        __threadfence();                       // acquire
    }
    __syncthreads();

    // --- softmax over S (256 threads, one score each; deterministic) ---
    float v = (tid < S_) ? g_scores[b * S_ + tid] : -1e30f;
    float m = v;
    #pragma unroll
    for (int o = 16; o; o >>= 1) m = fmaxf(m, __shfl_xor_sync(0xffffffffu, m, o));
    if (lane == 0) red[warp] = m;
    __syncthreads();
    if (tid == 0) {
        float mm = red[0];
        #pragma unroll
        for (int i = 1; i < 8; i++) mm = fmaxf(mm, red[i]);
        red[0] = mm;
    }
    __syncthreads();
    m = red[0];
    __syncthreads();

    float e = (tid < S_) ? __expf(v - m) : 0.f;
    float su = e;
    #pragma unroll
    for (int o = 16; o; o >>= 1) su += __shfl_xor_sync(0xffffffffu, su, o);
    if (lane == 0) red[warp] = su;
    __syncthreads();
    if (tid == 0) {
        float ss = 0.f;
        #pragma unroll
        for (int i = 0; i < 8; i++) ss += red[i];
        red[0] = ss;
    }
    __syncthreads();
    const float inv = 1.0f / red[0];
    if (tid < S_) {
        float wnorm = e * inv;
        ws[tid] = wnorm;
        if (q == 0) weight_out[b * S_ + tid] = wnorm;
    }
    __syncthreads();

    // --- direct pooling: this thread's r column (chunk q), all 196 s ---
    const int r = q * 256 + tid;
    const float* af = att_feats + (size_t)b * S_ * R_ + r;
    float acc = 0.f;
    #pragma unroll 7
    for (int s = 0; s < S_; s++) {
        acc = fmaf(ws[s], af[(size_t)s * R_], acc);
    }
    att_res[(size_t)b * R_ + r] = acc;
}

// ---------------------------------------------------------------------------
extern "C" void kernel_launch(void* const* d_in, const int* in_sizes, int n_in,
                              void* d_out, int out_size) {
    const float* att_feats = (const float*)d_in[0];  // [B,S,R]
    const float* p_att     = (const float*)d_in[1];  // [B,S,H]
    const float* hidden    = (const float*)d_in[2];  // [B,R]
    const float* in_w      = (const float*)d_in[3];  // [B,S]
    const float* h2w       = (const float*)d_in[4];  // [H,R]
    const float* h2b       = (const float*)d_in[5];  // [H]
    const float* aw        = (const float*)d_in[6];  // [1,H]
    const float* ab        = (const float*)d_in[7];  // [1]

    float* out     = (float*)d_out;
    float* att_res = out;                 // [B,R]
    float* weight  = out + B_ * R_;       // [B,S]

    k_h2att<<<dim3(H_ / BN, B_ / BM, KSPLIT), 256>>>(hidden, h2w, h2b);
    k_sp   <<<dim3(4, B_), 256>>>(p_att, in_w, aw, ab,
                                  att_feats, weight, att_res);
}